// round 7
// baseline (speedup 1.0000x reference)
#include <cuda_runtime.h>
#include <cstdint>

typedef unsigned long long ull;

#define B_   256
#define T_   512
#define IN_  64
#define H_   128
#define G_   512

__device__ float g_xg0[(size_t)T_ * B_ * G_];
__device__ float g_wt0[64 * 512];          // pre-transposed w_ih0: [k][g]

// ---------------- helpers ----------------
__device__ __forceinline__ uint32_t smem_u32(const void* p) {
    uint32_t a;
    asm("{ .reg .u64 t; cvta.to.shared.u64 t, %1; cvt.u32.u64 %0, t; }" : "=r"(a) : "l"(p));
    return a;
}
__device__ __forceinline__ uint32_t mapa_u32(uint32_t addr, uint32_t rank) {
    uint32_t r;
    asm("mapa.shared::cluster.u32 %0, %1, %2;" : "=r"(r) : "r"(addr), "r"(rank));
    return r;
}
__device__ __forceinline__ void stc_f32(uint32_t addr, float v) {
    asm volatile("st.shared::cluster.f32 [%0], %1;" :: "r"(addr), "f"(v));
}
#define CLUSTER_SYNC() do { \
    asm volatile("barrier.cluster.arrive.aligned;" ::: "memory"); \
    asm volatile("barrier.cluster.wait.aligned;"   ::: "memory"); } while (0)

__device__ __forceinline__ void mbar_init(uint32_t addr, uint32_t cnt) {
    asm volatile("mbarrier.init.shared.b64 [%0], %1;" :: "r"(addr), "r"(cnt) : "memory");
}
// remote arrive with release at cluster scope (orders this thread's prior remote stores)
__device__ __forceinline__ void mbar_arrive_rem(uint32_t addr) {
    asm volatile("mbarrier.arrive.release.cluster.shared::cluster.b64 _, [%0];"
                 :: "r"(addr) : "memory");
}
// local wait with acquire at cluster scope
__device__ __forceinline__ void mbar_wait_clu(uint32_t mbar, uint32_t parity) {
    asm volatile("{\n\t.reg .pred P;\nW%=:\n\t"
        "mbarrier.try_wait.parity.acquire.cluster.shared::cta.b64 P, [%0], %1, 0x989680;\n\t"
        "@P bra D%=;\n\tbra W%=;\nD%=:\n\t}" :: "r"(mbar), "r"(parity) : "memory");
}

__device__ __forceinline__ float sigf(float x)  { return 1.0f / (1.0f + __expf(-x)); }
__device__ __forceinline__ float tanh_f(float x){ return 1.0f - 2.0f / (__expf(2.0f * x) + 1.0f); }

__device__ __forceinline__ ull ffma2(ull a, ull b, ull c) {
    ull d; asm("fma.rn.f32x2 %0, %1, %2, %3;" : "=l"(d) : "l"(a), "l"(b), "l"(c)); return d;
}
__device__ __forceinline__ ull add2(ull a, ull b) {
    ull c; asm("add.rn.f32x2 %0, %1, %2;" : "=l"(c) : "l"(a), "l"(b)); return c;
}
__device__ __forceinline__ ull pack2(float x) {
    ull r; asm("mov.b64 %0, {%1, %1};" : "=l"(r) : "f"(x)); return r;
}
__device__ __forceinline__ float2 unpack2(ull v) {
    float2 f; asm("mov.b64 {%0, %1}, %2;" : "=f"(f.x), "=f"(f.y) : "l"(v)); return f;
}

// ---------------- pre-transpose for p1 ----------------
__global__ void pt_kernel(const float* __restrict__ w_ih0) {
    int i = blockIdx.x * 1024 + threadIdx.x;   // i = k*512 + g
    int k = i >> 9, g = i & 511;
    g_wt0[i] = w_ih0[g * 64 + k];
}

// ---------------- Phase 1: xg0 = x @ w_ih0^T + bias ----------------
#define P1_ROWS    64
#define P1_THREADS 256
#define P1_XT_STRIDE 68
#define P1_WT_OFF   0
#define P1_XT_OFF   (64*512)
#define P1_B_OFF    (P1_XT_OFF + 64*P1_XT_STRIDE)
#define P1_SMEM_FLOATS (P1_B_OFF + 512)

__global__ void __launch_bounds__(P1_THREADS)
p1_kernel(const float* __restrict__ x, const float* __restrict__ b_ih0,
          const float* __restrict__ b_hh0)
{
    extern __shared__ float s1[];
    float* WT   = s1 + P1_WT_OFF;
    float* xT   = s1 + P1_XT_OFF;
    float* bias = s1 + P1_B_OFF;
    const int tid = threadIdx.x;
    const int rowbase = blockIdx.x * P1_ROWS;

    // coalesced, conflict-free copy of pre-transposed W
    for (int idx = tid; idx < 64 * 512; idx += P1_THREADS) WT[idx] = g_wt0[idx];
    for (int g = tid; g < G_; g += P1_THREADS) bias[g] = b_ih0[g] + b_hh0[g];
    for (int idx = tid; idx < P1_ROWS * IN_ / 4; idx += P1_THREADS) {
        int row = idx >> 4, kq = idx & 15;
        float4 v = reinterpret_cast<const float4*>(x + (size_t)(rowbase + row) * IN_)[kq];
        int k = kq * 4;
        xT[(k + 0) * P1_XT_STRIDE + row] = v.x;
        xT[(k + 1) * P1_XT_STRIDE + row] = v.y;
        xT[(k + 2) * P1_XT_STRIDE + row] = v.z;
        xT[(k + 3) * P1_XT_STRIDE + row] = v.w;
    }
    __syncthreads();

    const int cg = tid & 63, rgq = tid >> 6;
    for (int it = 0; it < 4; ++it) {
        const int rg = it * 4 + rgq;
        ull a2[4][4];
        #pragma unroll
        for (int r = 0; r < 4; ++r)
            #pragma unroll
            for (int c = 0; c < 4; ++c) a2[r][c] = 0ull;
        #pragma unroll 4
        for (int k = 0; k < IN_; ++k) {
            float4 xv = *reinterpret_cast<const float4*>(xT + k * P1_XT_STRIDE + (rg << 2));
            ulonglong2 w0 = *reinterpret_cast<const ulonglong2*>(WT + (k << 9) + (cg << 2));
            ulonglong2 w1 = *reinterpret_cast<const ulonglong2*>(WT + (k << 9) + 256 + (cg << 2));
            ull xd0 = pack2(xv.x), xd1 = pack2(xv.y), xd2 = pack2(xv.z), xd3 = pack2(xv.w);
            a2[0][0] = ffma2(xd0, w0.x, a2[0][0]); a2[0][1] = ffma2(xd0, w0.y, a2[0][1]);
            a2[0][2] = ffma2(xd0, w1.x, a2[0][2]); a2[0][3] = ffma2(xd0, w1.y, a2[0][3]);
            a2[1][0] = ffma2(xd1, w0.x, a2[1][0]); a2[1][1] = ffma2(xd1, w0.y, a2[1][1]);
            a2[1][2] = ffma2(xd1, w1.x, a2[1][2]); a2[1][3] = ffma2(xd1, w1.y, a2[1][3]);
            a2[2][0] = ffma2(xd2, w0.x, a2[2][0]); a2[2][1] = ffma2(xd2, w0.y, a2[2][1]);
            a2[2][2] = ffma2(xd2, w1.x, a2[2][2]); a2[2][3] = ffma2(xd2, w1.y, a2[2][3]);
            a2[3][0] = ffma2(xd3, w0.x, a2[3][0]); a2[3][1] = ffma2(xd3, w0.y, a2[3][1]);
            a2[3][2] = ffma2(xd3, w1.x, a2[3][2]); a2[3][3] = ffma2(xd3, w1.y, a2[3][3]);
        }
        float4 bb0 = *reinterpret_cast<const float4*>(bias + (cg << 2));
        float4 bb1 = *reinterpret_cast<const float4*>(bias + 256 + (cg << 2));
        #pragma unroll
        for (int r = 0; r < 4; ++r) {
            int n = rowbase + rg * 4 + r;
            int b = n >> 9, t = n & 511;
            float* op = g_xg0 + ((size_t)t * B_ + b) * G_;
            float2 p0 = unpack2(a2[r][0]), p1v = unpack2(a2[r][1]);
            float2 p2 = unpack2(a2[r][2]), p3v = unpack2(a2[r][3]);
            *reinterpret_cast<float4*>(op + (cg << 2)) =
                make_float4(p0.x + bb0.x, p0.y + bb0.y, p1v.x + bb0.z, p1v.y + bb0.w);
            *reinterpret_cast<float4*>(op + 256 + (cg << 2)) =
                make_float4(p2.x + bb1.x, p2.y + bb1.y, p3v.x + bb1.z, p3v.y + bb1.w);
        }
    }
}

// ---------------- Phase 2: dual-stream warp-specialized scan ----------------
// 32 clusters x 4 CTAs x 512 threads. Each cluster: 8 batches = 2 streams of 4.
// Stream s = warps [8s, 8s+8): own gates, own H buffers, own named barrier
// (id 1+s), own DSMEM mbarriers (h0/h1 per step, 512 arrivals each).
// GEMM per stream: 256 threads, kc = stid&15 (16-way k-split), tile = stid>>4
// (rows tile*8..+7, all 4 batches). W smem layout identical to R3 (XOR swizzle).
#define SCT 512
#define CL_N 4
#define BPC  8
#define W0T_OFF 0          // floats, [k<<7 | swz], k 0..127
#define W1T_OFF 16384      // k 0..255 (0..127 w_ih1, 128..255 w_hh1)
#define HH_OFF  49152      // floats: 2 streams x [buf][k 0..255][b 0..3] = 2x2048
#define GT_OFF  53248      // floats: 2 streams x 128 rows x stride 5
#define B1_OFF  54528      // 128 floats
#define MB_OFF  218624     // BYTES: 2 streams x 2 mbarriers x 8 B
#define SC_SMEM_BYTES 218656

__device__ __forceinline__ void gemm4(const float* __restrict__ Wb,
                                      const float* __restrict__ hb,
                                      int kc, int tile, int k0, ull acc[16])
{
    #pragma unroll
    for (int ii = 0; ii < 8; ++ii) {
        int k = k0 + (ii << 4) + kc;
        const float* wr = Wb + (k << 7);
        int sw = k & 7;
        int g4 = tile << 1;
        ulonglong2 wA = *reinterpret_cast<const ulonglong2*>(wr + (((g4    ) ^ sw) << 2));
        ulonglong2 wB = *reinterpret_cast<const ulonglong2*>(wr + (((g4 | 1) ^ sw) << 2));
        float4 h = *reinterpret_cast<const float4*>(hb + (k << 2));
        ull h0 = pack2(h.x), h1 = pack2(h.y), h2 = pack2(h.z), h3 = pack2(h.w);
        acc[ 0] = ffma2(wA.x, h0, acc[ 0]); acc[ 1] = ffma2(wA.x, h1, acc[ 1]);
        acc[ 2] = ffma2(wA.x, h2, acc[ 2]); acc[ 3] = ffma2(wA.x, h3, acc[ 3]);
        acc[ 4] = ffma2(wA.y, h0, acc[ 4]); acc[ 5] = ffma2(wA.y, h1, acc[ 5]);
        acc[ 6] = ffma2(wA.y, h2, acc[ 6]); acc[ 7] = ffma2(wA.y, h3, acc[ 7]);
        acc[ 8] = ffma2(wB.x, h0, acc[ 8]); acc[ 9] = ffma2(wB.x, h1, acc[ 9]);
        acc[10] = ffma2(wB.x, h2, acc[10]); acc[11] = ffma2(wB.x, h3, acc[11]);
        acc[12] = ffma2(wB.y, h0, acc[12]); acc[13] = ffma2(wB.y, h1, acc[13]);
        acc[14] = ffma2(wB.y, h2, acc[14]); acc[15] = ffma2(wB.y, h3, acc[15]);
    }
}

// fold over 16 kc lanes (within 16-lane half-warp); lane kc ends with flat
// index bitrev4(kc) = rp*4 + b; stores rows tile*8+2rp, +2rp+1 of batch b.
__device__ __forceinline__ void fold_store4(ull F[16], float* __restrict__ gS,
                                            int kc, int tile)
{
    {   const bool hi = kc & 1;
        #pragma unroll
        for (int i = 0; i < 8; ++i) {
            ull give = hi ? F[i] : F[i + 8];
            ull keep = hi ? F[i + 8] : F[i];
            F[i] = add2(keep, __shfl_xor_sync(0xffffffffu, give, 1));
        } }
    {   const bool hi = kc & 2;
        #pragma unroll
        for (int i = 0; i < 4; ++i) {
            ull give = hi ? F[i] : F[i + 4];
            ull keep = hi ? F[i + 4] : F[i];
            F[i] = add2(keep, __shfl_xor_sync(0xffffffffu, give, 2));
        } }
    {   const bool hi = kc & 4;
        #pragma unroll
        for (int i = 0; i < 2; ++i) {
            ull give = hi ? F[i] : F[i + 2];
            ull keep = hi ? F[i + 2] : F[i];
            F[i] = add2(keep, __shfl_xor_sync(0xffffffffu, give, 4));
        } }
    {   const bool hi = kc & 8;
        ull give = hi ? F[0] : F[1];
        ull keep = hi ? F[1] : F[0];
        F[0] = add2(keep, __shfl_xor_sync(0xffffffffu, give, 8)); }
    const int rp = ((kc & 1) << 1) | ((kc >> 1) & 1);
    const int bb = (((kc >> 2) & 1) << 1) | ((kc >> 3) & 1);
    const int row0 = (tile << 3) + (rp << 1);
    float2 v = unpack2(F[0]);
    gS[row0 * 5 + bb]       = v.x;
    gS[(row0 + 1) * 5 + bb] = v.y;
}

__global__ void __launch_bounds__(SCT, 1) __cluster_dims__(CL_N, 1, 1)
scan_kernel(const float* __restrict__ w_hh0, const float* __restrict__ w_ih1,
            const float* __restrict__ w_hh1, const float* __restrict__ b_ih1,
            const float* __restrict__ b_hh1, const float* __restrict__ fc_w,
            const float* __restrict__ fc_b,  float* __restrict__ out)
{
    extern __shared__ float sm[];
    const uint32_t abase = smem_u32(sm);
    float* W0T   = sm + W0T_OFF;
    float* W1T   = sm + W1T_OFF;
    float* Hall  = sm + HH_OFF;
    float* GTall = sm + GT_OFF;
    float* bias1 = sm + B1_OFF;

    const int tid = threadIdx.x, wid = tid >> 5;
    uint32_t rank;
    asm("mov.u32 %0, %%cluster_ctarank;" : "=r"(rank));
    const int irank = (int)rank;
    const int cbase = (blockIdx.x >> 2) * BPC;

    // ---- prologue: W slices (R3 layout), bias, zero H, mbarriers ----
    for (int idx = tid; idx < 128 * 128; idx += SCT) {
        int rl = idx >> 7, k = idx & 127;
        int grow = ((rl >> 5) << 7) + irank * 32 + (rl & 31);
        int sa = (((rl >> 2) ^ (k & 7)) << 2) + (rl & 3);
        W0T[(k << 7) + sa]         = w_hh0[grow * H_ + k];
        W1T[(k << 7) + sa]         = w_ih1[grow * H_ + k];
        W1T[((128 + k) << 7) + sa] = w_hh1[grow * H_ + k];
    }
    for (int rl = tid; rl < 128; rl += SCT) {
        int grow = ((rl >> 5) << 7) + irank * 32 + (rl & 31);
        bias1[rl] = b_ih1[grow] + b_hh1[grow];
    }
    for (int i = tid; i < 4096; i += SCT) Hall[i] = 0.0f;
    if (tid == 0) {
        mbar_init(abase + MB_OFF + 0,  512);   // s0 h0
        mbar_init(abase + MB_OFF + 8,  512);   // s0 h1
        mbar_init(abase + MB_OFF + 16, 512);   // s1 h0
        mbar_init(abase + MB_OFF + 24, 512);   // s1 h1
    }
    __syncthreads();
    CLUSTER_SYNC();   // all CTAs' mbarriers + zeros visible before any remote op

    // remote bases
    uint32_t remH[4], remMB[4];
    #pragma unroll
    for (int r = 0; r < 4; ++r) {
        remH[r]  = mapa_u32(abase + HH_OFF * 4, (uint32_t)r);
        remMB[r] = mapa_u32(abase + MB_OFF, (uint32_t)r);
    }

    // ---- stream mapping ----
    const int s    = wid >> 3;           // stream 0/1
    const int stid = tid & 255;
    const int kc   = stid & 15;
    const int tile = stid >> 4;          // 0..15
    const int barid = 1 + s;
    float* HstS = Hall + s * 2048;       // [buf*1024 + k*4 + b]
    const uint32_t sHb = (uint32_t)(s * 8192);
    float* gS = GTall + s * 640;
    const uint32_t mbH0 = abase + MB_OFF + (uint32_t)(s * 16);
    const uint32_t mbH1 = mbH0 + 8;
    // ew mapping (stid < 128): one (batch, col) pair
    const int eb  = stid >> 5;           // 0..3
    const int ej  = stid & 31;
    const int col = irank * 32 + ej;
    const int gb  = cbase + s * 4 + eb;  // global batch

    float bi[4];
    #pragma unroll
    for (int q = 0; q < 4; ++q) bi[q] = bias1[q * 32 + ej];

    float c0 = 0.f, c1 = 0.f;
    ull acc0[16];
    #pragma unroll
    for (int i = 0; i < 16; ++i) acc0[i] = 0ull;
    gemm4(W0T, HstS, kc, tile, 0, acc0);           // t=0 reads buf0 (zeros)
    float xgv[4] = {0.f, 0.f, 0.f, 0.f};
    if (stid < 128) {
        const float* xp = g_xg0 + (size_t)gb * G_ + col;
        #pragma unroll
        for (int q = 0; q < 4; ++q) xgv[q] = __ldg(xp + q * 128);
    }

    for (int t = 0; t < T_; ++t) {
        const int p = t & 1;
        const int bufN = (1 - p) << 10;            // write buffer (floats)
        const int bufP = p << 10;                  // read buffer

        // ---- layer 0 ----
        fold_store4(acc0, gS, kc, tile);
        asm volatile("bar.sync %0, %1;" :: "r"(barid), "r"(256) : "memory");
        if (stid < 128) {
            float ai = gS[ej * 5 + eb]          + xgv[0];
            float af = gS[(32 + ej) * 5 + eb]   + xgv[1];
            float ag = gS[(64 + ej) * 5 + eb]   + xgv[2];
            float ao = gS[(96 + ej) * 5 + eb]   + xgv[3];
            float iv = sigf(ai), fv = sigf(af), gv = tanh_f(ag), ov = sigf(ao);
            c0 = fv * c0 + iv * gv;
            float h0 = ov * tanh_f(c0);
            uint32_t off = sHb + (uint32_t)((bufN + (col << 2) + eb) << 2);
            #pragma unroll
            for (int r = 0; r < 4; ++r) stc_f32(remH[r] + off, h0);
            #pragma unroll
            for (int r = 0; r < 4; ++r) mbar_arrive_rem(remMB[r] + (uint32_t)(s * 16));
        }
        // GEMM1b (h1_prev, k 128..255 of bufP): no wait needed (covered by h1bar(t-1))
        ull acc1[16];
        #pragma unroll
        for (int i = 0; i < 16; ++i) acc1[i] = 0ull;
        gemm4(W1T, HstS + bufP, kc, tile, 128, acc1);
        mbar_wait_clu(mbH0, (uint32_t)p);          // h0_new visible (all 4 CTAs)
        gemm4(W1T, HstS + bufN, kc, tile, 0, acc1);

        // ---- layer 1 ----
        fold_store4(acc1, gS, kc, tile);           // gates WAR safe: ew0 readers arrived pre-wait
        asm volatile("bar.sync %0, %1;" :: "r"(barid), "r"(256) : "memory");
        if (stid < 128) {
            float ai = gS[ej * 5 + eb]          + bi[0];
            float af = gS[(32 + ej) * 5 + eb]   + bi[1];
            float ag = gS[(64 + ej) * 5 + eb]   + bi[2];
            float ao = gS[(96 + ej) * 5 + eb]   + bi[3];
            float iv = sigf(ai), fv = sigf(af), gv = tanh_f(ag), ov = sigf(ao);
            c1 = fv * c1 + iv * gv;
            float h1 = ov * tanh_f(c1);
            uint32_t off = sHb + (uint32_t)((bufN + ((128 + col) << 2) + eb) << 2);
            #pragma unroll
            for (int r = 0; r < 4; ++r) stc_f32(remH[r] + off, h1);
            #pragma unroll
            for (int r = 0; r < 4; ++r) mbar_arrive_rem(remMB[r] + (uint32_t)(s * 16 + 8));
        }
        // next step's GEMM0 (h0_new, already waited) + xg prefetch overlap h1 wait
        #pragma unroll
        for (int i = 0; i < 16; ++i) acc0[i] = 0ull;
        gemm4(W0T, HstS + bufN, kc, tile, 0, acc0);
        if (stid < 128) {
            const int tn = (t + 1) & 511;
            const float* xp = g_xg0 + ((size_t)tn * B_ + gb) * G_ + col;
            #pragma unroll
            for (int q = 0; q < 4; ++q) xgv[q] = __ldg(xp + q * 128);
        }
        mbar_wait_clu(mbH1, (uint32_t)p);          // h1_new visible; orders next GEMM1b + gates WAR
    }

    // ---- epilogue: final h1 (t=511 wrote buf0, rows 128..255, local copy) ----
    if (irank == 0 && stid < 32) {
        const int lane = stid;
        float fcw[4];
        #pragma unroll
        for (int cc = 0; cc < 4; ++cc) fcw[cc] = __ldg(fc_w + lane * 4 + cc);
        const float fcb = __ldg(fc_b);
        for (int b = 0; b < 4; ++b) {
            float ssum = 0.0f;
            #pragma unroll
            for (int cc = 0; cc < 4; ++cc) {
                int c = lane * 4 + cc;
                ssum += HstS[((128 + c) << 2) + b] * fcw[cc];
            }
            #pragma unroll
            for (int d = 16; d > 0; d >>= 1)
                ssum += __shfl_xor_sync(0xffffffffu, ssum, d);
            if (lane == 0) out[cbase + s * 4 + b] = ssum + fcb;
        }
    }
    CLUSTER_SYNC();   // no CTA exits while peers may still reference its smem
}

// ---------------------------------------------------------------------------
extern "C" void kernel_launch(void* const* d_in, const int* in_sizes, int n_in,
                              void* d_out, int out_size)
{
    const float* x     = (const float*)d_in[0];
    const float* w_ih0 = (const float*)d_in[1];
    const float* w_hh0 = (const float*)d_in[2];
    const float* b_ih0 = (const float*)d_in[3];
    const float* b_hh0 = (const float*)d_in[4];
    const float* w_ih1 = (const float*)d_in[5];
    const float* w_hh1 = (const float*)d_in[6];
    const float* b_ih1 = (const float*)d_in[7];
    const float* b_hh1 = (const float*)d_in[8];
    const float* fc_w  = (const float*)d_in[9];
    const float* fc_b  = (const float*)d_in[10];
    float* out = (float*)d_out;

    const int p1_smem = P1_SMEM_FLOATS * 4;
    cudaFuncSetAttribute(p1_kernel,   cudaFuncAttributeMaxDynamicSharedMemorySize, p1_smem);
    cudaFuncSetAttribute(scan_kernel, cudaFuncAttributeMaxDynamicSharedMemorySize, SC_SMEM_BYTES);

    pt_kernel<<<32, 1024>>>(w_ih0);
    p1_kernel<<<(B_ * T_) / P1_ROWS, P1_THREADS, p1_smem>>>(x, b_ih0, b_hh0);
    scan_kernel<<<(B_ / BPC) * CL_N, SCT, SC_SMEM_BYTES>>>(
        w_hh0, w_ih1, w_hh1, b_ih1, b_hh1, fc_w, fc_b, out);
}

// round 8
// speedup vs baseline: 1.1973x; 1.1973x over previous
#include <cuda_runtime.h>
#include <cstdint>

typedef unsigned long long ull;

#define B_   256
#define T_   512
#define IN_  64
#define H_   128
#define G_   512

__device__ float g_xg0[(size_t)T_ * B_ * G_];
__device__ float g_wt0[64 * 512];          // pre-transposed w_ih0: [k][g]

// ---------------- helpers ----------------
__device__ __forceinline__ uint32_t smem_u32(const void* p) {
    uint32_t a;
    asm("{ .reg .u64 t; cvta.to.shared.u64 t, %1; cvt.u32.u64 %0, t; }" : "=r"(a) : "l"(p));
    return a;
}
__device__ __forceinline__ uint32_t mapa_u32(uint32_t addr, uint32_t rank) {
    uint32_t r;
    asm("mapa.shared::cluster.u32 %0, %1, %2;" : "=r"(r) : "r"(addr), "r"(rank));
    return r;
}
__device__ __forceinline__ void stc_f32(uint32_t addr, float v) {
    asm volatile("st.shared::cluster.f32 [%0], %1;" :: "r"(addr), "f"(v));
}
#define CLUSTER_ARRIVE() asm volatile("barrier.cluster.arrive.aligned;" ::: "memory")
#define CLUSTER_WAIT()   asm volatile("barrier.cluster.wait.aligned;"   ::: "memory")
#define CLUSTER_SYNC() do { CLUSTER_ARRIVE(); CLUSTER_WAIT(); } while (0)

__device__ __forceinline__ float sigf(float x)  { return 1.0f / (1.0f + __expf(-x)); }
__device__ __forceinline__ float tanh_f(float x){ return 1.0f - 2.0f / (__expf(2.0f * x) + 1.0f); }

__device__ __forceinline__ ull ffma2(ull a, ull b, ull c) {
    ull d; asm("fma.rn.f32x2 %0, %1, %2, %3;" : "=l"(d) : "l"(a), "l"(b), "l"(c)); return d;
}
__device__ __forceinline__ ull add2(ull a, ull b) {
    ull c; asm("add.rn.f32x2 %0, %1, %2;" : "=l"(c) : "l"(a), "l"(b)); return c;
}
__device__ __forceinline__ ull pack2(float x) {
    ull r; asm("mov.b64 %0, {%1, %1};" : "=l"(r) : "f"(x)); return r;
}
__device__ __forceinline__ float2 unpack2(ull v) {
    float2 f; asm("mov.b64 {%0, %1}, %2;" : "=f"(f.x), "=f"(f.y) : "l"(v)); return f;
}

// ---------------- pre-transpose for p1 (fixes 32-way conflict) ----------------
__global__ void pt_kernel(const float* __restrict__ w_ih0) {
    int i = blockIdx.x * 1024 + threadIdx.x;   // i = k*512 + g
    int k = i >> 9, g = i & 511;
    g_wt0[i] = w_ih0[g * 64 + k];
}

// ---------------- Phase 1: xg0 = x @ w_ih0^T + bias ----------------
#define P1_ROWS    64
#define P1_THREADS 256
#define P1_XT_STRIDE 68
#define P1_WT_OFF   0
#define P1_XT_OFF   (64*512)
#define P1_B_OFF    (P1_XT_OFF + 64*P1_XT_STRIDE)
#define P1_SMEM_FLOATS (P1_B_OFF + 512)

__global__ void __launch_bounds__(P1_THREADS)
p1_kernel(const float* __restrict__ x, const float* __restrict__ b_ih0,
          const float* __restrict__ b_hh0)
{
    extern __shared__ float s1[];
    float* WT   = s1 + P1_WT_OFF;
    float* xT   = s1 + P1_XT_OFF;
    float* bias = s1 + P1_B_OFF;
    const int tid = threadIdx.x;
    const int rowbase = blockIdx.x * P1_ROWS;

    for (int idx = tid; idx < 64 * 512; idx += P1_THREADS) WT[idx] = g_wt0[idx];
    for (int g = tid; g < G_; g += P1_THREADS) bias[g] = b_ih0[g] + b_hh0[g];
    for (int idx = tid; idx < P1_ROWS * IN_ / 4; idx += P1_THREADS) {
        int row = idx >> 4, kq = idx & 15;
        float4 v = reinterpret_cast<const float4*>(x + (size_t)(rowbase + row) * IN_)[kq];
        int k = kq * 4;
        xT[(k + 0) * P1_XT_STRIDE + row] = v.x;
        xT[(k + 1) * P1_XT_STRIDE + row] = v.y;
        xT[(k + 2) * P1_XT_STRIDE + row] = v.z;
        xT[(k + 3) * P1_XT_STRIDE + row] = v.w;
    }
    __syncthreads();

    const int cg = tid & 63, rgq = tid >> 6;
    for (int it = 0; it < 4; ++it) {
        const int rg = it * 4 + rgq;
        ull a2[4][4];
        #pragma unroll
        for (int r = 0; r < 4; ++r)
            #pragma unroll
            for (int c = 0; c < 4; ++c) a2[r][c] = 0ull;
        #pragma unroll 4
        for (int k = 0; k < IN_; ++k) {
            float4 xv = *reinterpret_cast<const float4*>(xT + k * P1_XT_STRIDE + (rg << 2));
            ulonglong2 w0 = *reinterpret_cast<const ulonglong2*>(WT + (k << 9) + (cg << 2));
            ulonglong2 w1 = *reinterpret_cast<const ulonglong2*>(WT + (k << 9) + 256 + (cg << 2));
            ull xd0 = pack2(xv.x), xd1 = pack2(xv.y), xd2 = pack2(xv.z), xd3 = pack2(xv.w);
            a2[0][0] = ffma2(xd0, w0.x, a2[0][0]); a2[0][1] = ffma2(xd0, w0.y, a2[0][1]);
            a2[0][2] = ffma2(xd0, w1.x, a2[0][2]); a2[0][3] = ffma2(xd0, w1.y, a2[0][3]);
            a2[1][0] = ffma2(xd1, w0.x, a2[1][0]); a2[1][1] = ffma2(xd1, w0.y, a2[1][1]);
            a2[1][2] = ffma2(xd1, w1.x, a2[1][2]); a2[1][3] = ffma2(xd1, w1.y, a2[1][3]);
            a2[2][0] = ffma2(xd2, w0.x, a2[2][0]); a2[2][1] = ffma2(xd2, w0.y, a2[2][1]);
            a2[2][2] = ffma2(xd2, w1.x, a2[2][2]); a2[2][3] = ffma2(xd2, w1.y, a2[2][3]);
            a2[3][0] = ffma2(xd3, w0.x, a2[3][0]); a2[3][1] = ffma2(xd3, w0.y, a2[3][1]);
            a2[3][2] = ffma2(xd3, w1.x, a2[3][2]); a2[3][3] = ffma2(xd3, w1.y, a2[3][3]);
        }
        float4 bb0 = *reinterpret_cast<const float4*>(bias + (cg << 2));
        float4 bb1 = *reinterpret_cast<const float4*>(bias + 256 + (cg << 2));
        #pragma unroll
        for (int r = 0; r < 4; ++r) {
            int n = rowbase + rg * 4 + r;
            int b = n >> 9, t = n & 511;
            float* op = g_xg0 + ((size_t)t * B_ + b) * G_;
            float2 p0 = unpack2(a2[r][0]), p1v = unpack2(a2[r][1]);
            float2 p2 = unpack2(a2[r][2]), p3v = unpack2(a2[r][3]);
            *reinterpret_cast<float4*>(op + (cg << 2)) =
                make_float4(p0.x + bb0.x, p0.y + bb0.y, p1v.x + bb0.z, p1v.y + bb0.w);
            *reinterpret_cast<float4*>(op + 256 + (cg << 2)) =
                make_float4(p2.x + bb1.x, p2.y + bb1.y, p3v.x + bb1.z, p3v.y + bb1.w);
        }
    }
}

// ---------------- Phase 2: R4 scan + affine conflict-free W (stride 132) ----
// 32 clusters x 4 CTAs x 512 threads; 8 batches/cluster; CTA rank owns cols
// [r*32, r*32+32). W k-major stride WS=132 floats (528 B; 528 mod 128B = 16B
// so the 8 kc-lanes of every LDS.128 phase hit 8 distinct 16B bank groups —
// conflict-free AND affine in k). H [buf][k][b] stride 12. gates [row][b]
// stride 9. Rotated pipeline with split cluster barriers (same as R4).
#define SC_THREADS 512
#define CL_N 4
#define BPC  8
#define WS   132
#define HS   12
#define GS   9
#define W0T_OFF 0
#define W1T_OFF (128*WS)                  // 16896
#define H_OFF   (W1T_OFF + 256*WS)        // 50688
#define GT_OFF  (H_OFF + 2*256*HS)        // 56832
#define SC_SMEM_FLOATS (GT_OFF + 128*GS)  // 57984 -> 231936 B

__device__ __forceinline__ void gemm_half(const float* __restrict__ Wb,
                                          const float* __restrict__ hb,
                                          int kc, int rg, int bg, int k0,
                                          ull acc[16])
{
    #pragma unroll
    for (int ii = 0; ii < 8; ++ii) {
        int k = k0 + (ii << 4) + kc;
        const float* wr = Wb + k * WS + (rg << 3);
        ulonglong2 wA = *reinterpret_cast<const ulonglong2*>(wr);       // rows 8rg..+3
        ulonglong2 wB = *reinterpret_cast<const ulonglong2*>(wr + 4);   // rows 8rg+4..+7
        float4 h = *reinterpret_cast<const float4*>(hb + k * HS + (bg << 2));
        ull h0 = pack2(h.x), h1 = pack2(h.y), h2 = pack2(h.z), h3 = pack2(h.w);
        acc[ 0] = ffma2(wA.x, h0, acc[ 0]); acc[ 1] = ffma2(wA.x, h1, acc[ 1]);
        acc[ 2] = ffma2(wA.x, h2, acc[ 2]); acc[ 3] = ffma2(wA.x, h3, acc[ 3]);
        acc[ 4] = ffma2(wA.y, h0, acc[ 4]); acc[ 5] = ffma2(wA.y, h1, acc[ 5]);
        acc[ 6] = ffma2(wA.y, h2, acc[ 6]); acc[ 7] = ffma2(wA.y, h3, acc[ 7]);
        acc[ 8] = ffma2(wB.x, h0, acc[ 8]); acc[ 9] = ffma2(wB.x, h1, acc[ 9]);
        acc[10] = ffma2(wB.x, h2, acc[10]); acc[11] = ffma2(wB.x, h3, acc[11]);
        acc[12] = ffma2(wB.y, h0, acc[12]); acc[13] = ffma2(wB.y, h1, acc[13]);
        acc[14] = ffma2(wB.y, h2, acc[14]); acc[15] = ffma2(wB.y, h3, acc[15]);
    }
}

__device__ __forceinline__ void fold_store(ull F[16], float* __restrict__ gates,
                                           int kc, int rg, int bg)
{
    {   const bool hi = kc & 1;
        #pragma unroll
        for (int i = 0; i < 8; ++i) {
            ull give = hi ? F[i] : F[i + 8];
            ull keep = hi ? F[i + 8] : F[i];
            F[i] = add2(keep, __shfl_xor_sync(0xffffffffu, give, 1));
        } }
    {   const bool hi = kc & 2;
        #pragma unroll
        for (int i = 0; i < 4; ++i) {
            ull give = hi ? F[i] : F[i + 4];
            ull keep = hi ? F[i + 4] : F[i];
            F[i] = add2(keep, __shfl_xor_sync(0xffffffffu, give, 2));
        } }
    {   const bool hi = kc & 4;
        #pragma unroll
        for (int i = 0; i < 2; ++i) {
            ull give = hi ? F[i] : F[i + 2];
            ull keep = hi ? F[i + 2] : F[i];
            F[i] = add2(keep, __shfl_xor_sync(0xffffffffu, give, 4));
        } }
    {   const bool hi = kc & 8;
        ull give = hi ? F[0] : F[1];
        ull keep = hi ? F[1] : F[0];
        F[0] = add2(keep, __shfl_xor_sync(0xffffffffu, give, 8)); }
    const int rp = ((kc & 1) << 1) | ((kc >> 1) & 1);
    const int bb = (((kc >> 2) & 1) << 1) | ((kc >> 3) & 1);
    const int row0 = (rg << 3) + (rp << 1);
    float2 v = unpack2(F[0]);
    gates[row0 * GS + (bg << 2) + bb]       = v.x;
    gates[(row0 + 1) * GS + (bg << 2) + bb] = v.y;
}

__global__ void __launch_bounds__(SC_THREADS, 1) __cluster_dims__(CL_N, 1, 1)
scan_kernel(const float* __restrict__ w_hh0, const float* __restrict__ w_ih1,
            const float* __restrict__ w_hh1, const float* __restrict__ b_ih1,
            const float* __restrict__ b_hh1, const float* __restrict__ fc_w,
            const float* __restrict__ fc_b,  float* __restrict__ out)
{
    extern __shared__ float s2[];
    float* W0T   = s2 + W0T_OFF;
    float* W1T   = s2 + W1T_OFF;   // k 0..127 = w_ih1, 128..255 = w_hh1
    float* Hbuf  = s2 + H_OFF;     // [buf][k 0..255][b] stride HS; k<128 h0 else h1
    float* gates = s2 + GT_OFF;    // [row][b] stride GS

    const int tid = threadIdx.x;
    uint32_t rank;
    asm("mov.u32 %0, %%cluster_ctarank;" : "=r"(rank));
    const int irank = (int)rank;
    const int cbase = (blockIdx.x >> 2) * BPC;

    // ---- prologue: W slices k-major stride WS (rows rl 0..127 contiguous) ----
    for (int idx = tid; idx < 128 * 128; idx += SC_THREADS) {
        int rl = idx >> 7, k = idx & 127;
        int grow = ((rl >> 5) << 7) + irank * 32 + (rl & 31);
        W0T[k * WS + rl]         = w_hh0[grow * H_ + k];
        W1T[k * WS + rl]         = w_ih1[grow * H_ + k];
        W1T[(128 + k) * WS + rl] = w_hh1[grow * H_ + k];
    }
    for (int i = tid; i < 2 * 256 * HS; i += SC_THREADS) Hbuf[i] = 0.0f;

    const uint32_t hloc = smem_u32(Hbuf);
    uint32_t hrem[4];
    #pragma unroll
    for (int r = 0; r < 4; ++r) hrem[r] = mapa_u32(hloc, (uint32_t)r);

    // GEMM mapping
    const int kc = tid & 15;
    const int tl = tid >> 4;
    const int bg = tl & 1;
    const int rg = tl >> 1;
    // elementwise mapping (tid < 256)
    const int eb  = tid >> 5;
    const int ej  = tid & 31;
    const int col = irank * 32 + ej;
    const float* xgbase = g_xg0 + (size_t)(cbase + eb) * G_ + col;

    // layer-1 bias in registers (ew threads only)
    float bi1i = 0.f, bi1f = 0.f, bi1g = 0.f, bi1o = 0.f;
    if (tid < 256) {
        bi1i = __ldg(b_ih1 + col)           + __ldg(b_hh1 + col);
        bi1f = __ldg(b_ih1 + 128 + col)     + __ldg(b_hh1 + 128 + col);
        bi1g = __ldg(b_ih1 + 256 + col)     + __ldg(b_hh1 + 256 + col);
        bi1o = __ldg(b_ih1 + 384 + col)     + __ldg(b_hh1 + 384 + col);
    }

    CLUSTER_SYNC();

    float c0 = 0.0f, c1 = 0.0f;
    ull acc0[16];

    #pragma unroll
    for (int i = 0; i < 16; ++i) acc0[i] = 0ull;
    gemm_half(W0T, Hbuf, kc, rg, bg, 0, acc0);   // t=0: h0_prev = zeros (buf 0)
    float xg_i = 0.f, xg_f = 0.f, xg_g = 0.f, xg_o = 0.f;
    if (tid < 256) {
        xg_i = __ldg(xgbase);
        xg_f = __ldg(xgbase + 128);
        xg_g = __ldg(xgbase + 256);
        xg_o = __ldg(xgbase + 384);
    }

    for (int t = 0; t < T_; ++t) {
        const int p = t & 1;
        const int bufP = p ? 3072 : 0;        // holds h0_prev / h1_prev
        const int bufN = p ? 0 : 3072;        // receives h0_new / h1_new

        // ---- publish gates0, elementwise layer 0 ----
        fold_store(acc0, gates, kc, rg, bg);
        __syncthreads();
        if (tid < 256) {
            float gi = gates[ej * GS + eb]        + xg_i;
            float gf = gates[(32 + ej) * GS + eb] + xg_f;
            float gg = gates[(64 + ej) * GS + eb] + xg_g;
            float go = gates[(96 + ej) * GS + eb] + xg_o;
            float iv = sigf(gi), fv = sigf(gf), gv = tanh_f(gg), ov = sigf(go);
            c0 = fv * c0 + iv * gv;
            float h0 = ov * tanh_f(c0);
            uint32_t off = (uint32_t)((bufN + col * HS + eb) << 2);
            #pragma unroll
            for (int r = 0; r < 4; ++r) stc_f32(hrem[r] + off, h0);
        }
        CLUSTER_ARRIVE();                          // W0: h0_new release

        // ---- GEMM1b (h1_prev) overlaps barrier W0 ----
        ull acc1[16];
        #pragma unroll
        for (int i = 0; i < 16; ++i) acc1[i] = 0ull;
        gemm_half(W1T, Hbuf + bufP, kc, rg, bg, 128, acc1);

        CLUSTER_WAIT();                            // h0_new visible cluster-wide

        // ---- GEMM1a (h0_new) + publish gates1 ----
        gemm_half(W1T, Hbuf + bufN, kc, rg, bg, 0, acc1);
        fold_store(acc1, gates, kc, rg, bg);
        __syncthreads();

        // ---- elementwise layer 1 ----
        if (tid < 256) {
            float gi = gates[ej * GS + eb]        + bi1i;
            float gf = gates[(32 + ej) * GS + eb] + bi1f;
            float gg = gates[(64 + ej) * GS + eb] + bi1g;
            float go = gates[(96 + ej) * GS + eb] + bi1o;
            float iv = sigf(gi), fv = sigf(gf), gv = tanh_f(gg), ov = sigf(go);
            c1 = fv * c1 + iv * gv;
            float h1 = ov * tanh_f(c1);
            uint32_t off = (uint32_t)((bufN + (128 + col) * HS + eb) << 2);
            #pragma unroll
            for (int r = 0; r < 4; ++r) stc_f32(hrem[r] + off, h1);
        }
        CLUSTER_ARRIVE();                          // W1: h1_new release

        // ---- next step's GEMM0 + xg prefetch overlap barrier W1 ----
        if (t + 1 < T_) {
            #pragma unroll
            for (int i = 0; i < 16; ++i) acc0[i] = 0ull;
            gemm_half(W0T, Hbuf + bufN, kc, rg, bg, 0, acc0);
            if (tid < 256) {
                const float* xgp = xgbase + (size_t)(t + 1) * (B_ * G_);
                xg_i = __ldg(xgp);
                xg_f = __ldg(xgp + 128);
                xg_g = __ldg(xgp + 256);
                xg_o = __ldg(xgp + 384);
            }
        }
        CLUSTER_WAIT();                            // h1_new visible; full barrier
    }

    // ---- epilogue: out[b] = fc_b + sum_c h1_last[b][c] * fc_w[c] ----
    // t=511: p=1, bufN=0 -> final h1 in buffer 0, rows 128..255
    if (irank == 0 && tid < 256) {
        const int b = tid >> 5;
        const int l = tid & 31;
        float ssum = 0.0f;
        #pragma unroll
        for (int cc = 0; cc < 4; ++cc) {
            int c = l * 4 + cc;
            ssum += Hbuf[(128 + c) * HS + b] * __ldg(fc_w + c);
        }
        #pragma unroll
        for (int d = 16; d > 0; d >>= 1)
            ssum += __shfl_xor_sync(0xffffffffu, ssum, d);
        if (l == 0) out[cbase + b] = ssum + __ldg(fc_b);
    }
    CLUSTER_SYNC();
}

// ---------------------------------------------------------------------------
extern "C" void kernel_launch(void* const* d_in, const int* in_sizes, int n_in,
                              void* d_out, int out_size)
{
    const float* x     = (const float*)d_in[0];
    const float* w_ih0 = (const float*)d_in[1];
    const float* w_hh0 = (const float*)d_in[2];
    const float* b_ih0 = (const float*)d_in[3];
    const float* b_hh0 = (const float*)d_in[4];
    const float* w_ih1 = (const float*)d_in[5];
    const float* w_hh1 = (const float*)d_in[6];
    const float* b_ih1 = (const float*)d_in[7];
    const float* b_hh1 = (const float*)d_in[8];
    const float* fc_w  = (const float*)d_in[9];
    const float* fc_b  = (const float*)d_in[10];
    float* out = (float*)d_out;

    const int p1_smem = P1_SMEM_FLOATS * 4;
    const int sc_smem = SC_SMEM_FLOATS * 4;
    cudaFuncSetAttribute(p1_kernel,   cudaFuncAttributeMaxDynamicSharedMemorySize, p1_smem);
    cudaFuncSetAttribute(scan_kernel, cudaFuncAttributeMaxDynamicSharedMemorySize, sc_smem);

    pt_kernel<<<32, 1024>>>(w_ih0);
    p1_kernel<<<(B_ * T_) / P1_ROWS, P1_THREADS, p1_smem>>>(x, b_ih0, b_hh0);
    scan_kernel<<<(B_ / BPC) * CL_N, SC_THREADS, sc_smem>>>(
        w_hh0, w_ih1, w_hh1, b_ih1, b_hh1, fc_w, fc_b, out);
}